// round 1
// baseline (speedup 1.0000x reference)
#include <cuda_runtime.h>
#include <math.h>

typedef unsigned long long ull;

// ---------------- scratch (device globals; no allocations allowed) ----------------
__device__ float g_qT  [1024 * 256];      // [b*128+r][e]   e = h*16+d
__device__ float g_kTT [8 * 256 * 128];   // [b][e][c]
__device__ float g_v1  [1024 * 256];      // [b][h][s][d]
__device__ float g_v2  [1024 * 256];      // [b][h][s][d]
__device__ float g_ms1 [2097152];         // [b][h][r][c]
__device__ float g_ms2 [2097152];         // [b][h][r][c]
__device__ float g_attn1[1024 * 256];     // [b*128+r][h*16+d]
__device__ float g_attn2[1024 * 256];     // [b*128+c][h*16+d]
__device__ float g_part[1024 * 4];        // per-block {s1,q1,s2,q2}
__device__ float g_stats[2];              // inv_std1, inv_std2

// ---------------- f32x2 packed helpers (Blackwell sm_100+) ----------------
__device__ __forceinline__ ull pack2(float lo, float hi) {
    ull r; asm("mov.b64 %0, {%1, %2};" : "=l"(r) : "f"(lo), "f"(hi)); return r;
}
__device__ __forceinline__ void unpack2(ull v, float& lo, float& hi) {
    asm("mov.b64 {%0, %1}, %2;" : "=f"(lo), "=f"(hi) : "l"(v));
}
__device__ __forceinline__ ull fma2(ull a, ull b, ull c) {
    ull d; asm("fma.rn.f32x2 %0, %1, %2, %3;" : "=l"(d) : "l"(a), "l"(b), "l"(c)); return d;
}
__device__ __forceinline__ ull mul2(ull a, ull b) {
    ull d; asm("mul.rn.f32x2 %0, %1, %2;" : "=l"(d) : "l"(a), "l"(b)); return d;
}

// ---------------- K1: qkv projection GEMM ----------------
// M=2048 (x1 rows then x2 rows), N=512, K=256. 32x64 tiles, 256 threads.
#define SM_QKV ((32 * 260 + 256 * 64) * 4)
__global__ void k_qkv(const float* __restrict__ x1, const float* __restrict__ x2,
                      const float* __restrict__ W) {
    extern __shared__ float smq[];
    float* sA = smq;             // 32 x 260 (padded)
    float* sB = smq + 32 * 260;  // 256 x 64
    const int m0 = blockIdx.x * 32, n0 = blockIdx.y * 64;
    const bool isX1 = (m0 < 1024);
    const float* src = isX1 ? x1 : x2;
    const int mm = m0 & 1023;
    const int b = mm >> 7, s0 = mm & 127;
    const int tid = threadIdx.x;

    for (int idx = tid; idx < 2048; idx += 256) {
        int row = idx >> 6, kk = (idx & 63) << 2;
        float4 v = *(const float4*)(src + (b * 128 + s0 + row) * 256 + kk);
        *(float4*)(sA + row * 260 + kk) = v;
    }
    for (int idx = tid; idx < 4096; idx += 256) {
        int row = idx >> 4, c4 = (idx & 15) << 2;
        float4 v = *(const float4*)(W + row * 512 + n0 + c4);
        *(float4*)(sB + row * 64 + c4) = v;
    }
    __syncthreads();

    const int r = tid >> 3, cg = tid & 7;
    float acc[8];
#pragma unroll
    for (int j = 0; j < 8; j++) acc[j] = 0.f;
    const float4* sB4 = (const float4*)sB;
#pragma unroll 4
    for (int k = 0; k < 256; k++) {
        float a = sA[r * 260 + k];
        float4 b0 = sB4[k * 16 + cg * 2];
        float4 b1 = sB4[k * 16 + cg * 2 + 1];
        acc[0] += a * b0.x; acc[1] += a * b0.y; acc[2] += a * b0.z; acc[3] += a * b0.w;
        acc[4] += a * b1.x; acc[5] += a * b1.y; acc[6] += a * b1.z; acc[7] += a * b1.w;
    }

    const int s = s0 + r;
#pragma unroll
    for (int j = 0; j < 8; j++) {
        int n = n0 + cg * 8 + j;
        float v = acc[j];
        if (n < 256) {
            if (isX1) g_qT[(b * 128 + s) * 256 + n] = v;
            else      g_kTT[(b * 256 + n) * 128 + s] = v;
        } else {
            int h = (n - 256) >> 4, d = n & 15;
            float* dst = isX1 ? g_v1 : g_v2;
            dst[((b * 16 + h) * 128 + s) * 16 + d] = v;
        }
    }
}

// ---------------- K3: fused dot + MixedScoreFF MLP ----------------
// grid 1024 = (b,r), block 128 = c. f32x2 packed MLP, weights in SMEM.
#define SM_MLP 101376
__global__ void k_mlp(const float* __restrict__ cost, const float* __restrict__ w1,
                      const float* __restrict__ w2) {
    extern __shared__ char smm[];
    ull*   sw1p = (ull*)smm;                  // [kp=256][h=16]  pairs of W1 even-row cols
    ull*   scbp = (ull*)(smm + 32768);        // [256] cost-bias pairs
    ull*   sw2  = (ull*)(smm + 34816);        // [512][16] lin2 rows as float2 pairs
    float* sq   = (float*)(smm + 100352);     // [256] q row

    const int blk = blockIdx.x;
    const int b = blk >> 7, r = blk & 127;
    const int tid = threadIdx.x;

    for (int idx = tid; idx < 4096; idx += 128) {
        int h = idx >> 8, kp = idx & 255;
        sw1p[kp * 16 + h] = *(const ull*)(w1 + h * 1024 + 2 * kp);
    }
    for (int kp = tid; kp < 256; kp += 128) {
        float c0 = 0.f, c1 = 0.f;
#pragma unroll
        for (int h = 0; h < 16; h++) {
            c0 += w1[(2 * h + 1) * 512 + 2 * kp];
            c1 += w1[(2 * h + 1) * 512 + 2 * kp + 1];
        }
        scbp[kp] = pack2(c0, c1);
    }
    {
        const ull* w2u = (const ull*)w2;
        for (int idx = tid; idx < 8192; idx += 128) sw2[idx] = w2u[idx];
    }
    for (int idx = tid; idx < 256; idx += 128) sq[idx] = g_qT[(blk << 8) + idx];
    __syncthreads();

    const int c = tid;
    // dot logits: din[h] = 0.25 * sum_d q[h,d] * k[h,d]
    float din[16];
    const float* kbase = g_kTT + b * 32768 + c;
#pragma unroll
    for (int h = 0; h < 16; h++) {
        float a = 0.f;
#pragma unroll
        for (int d = 0; d < 16; d++) a += sq[h * 16 + d] * kbase[(h * 16 + d) * 128];
        din[h] = a * 0.25f;
    }
    ull din2[16];
#pragma unroll
    for (int h = 0; h < 16; h++) din2[h] = pack2(din[h], din[h]);
    float cv = cost[blk * 128 + c];
    ull cost2 = pack2(cv, cv);

    ull o2[16];
#pragma unroll
    for (int j = 0; j < 16; j++) o2[j] = 0ull;

#pragma unroll 4
    for (int kp = 0; kp < 256; kp++) {
        ull hp = mul2(cost2, scbp[kp]);
        const ull* w1c = sw1p + kp * 16;
#pragma unroll
        for (int h = 0; h < 16; h++) hp = fma2(din2[h], w1c[h], hp);
        float h0, h1; unpack2(hp, h0, h1);
        h0 = fmaxf(h0, 0.f); h1 = fmaxf(h1, 0.f);
        ull h0x = pack2(h0, h0), h1x = pack2(h1, h1);
        const ull* w2a = sw2 + (kp * 2) * 16;
        const ull* w2b = w2a + 16;
#pragma unroll
        for (int j = 0; j < 16; j++) {
            o2[j] = fma2(h0x, w2a[j], o2[j]);
            o2[j] = fma2(h1x, w2b[j], o2[j]);
        }
    }

    float s1 = 0.f, q1 = 0.f, s2 = 0.f, q2 = 0.f;
#pragma unroll
    for (int h = 0; h < 16; h++) {
        float m1, m2; unpack2(o2[h], m1, m2);
        int idx = ((b * 16 + h) * 128 + r) * 128 + c;
        g_ms1[idx] = m1;
        g_ms2[idx] = m2;
        s1 += m1; q1 += m1 * m1; s2 += m2; q2 += m2 * m2;
    }

    // block reduce -> g_part
    float v[4] = {s1, q1, s2, q2};
#pragma unroll
    for (int i = 0; i < 4; i++)
        for (int off = 16; off; off >>= 1) v[i] += __shfl_xor_sync(0xffffffffu, v[i], off);
    __shared__ float red[4][4];
    int w = tid >> 5, lane = tid & 31;
    if (lane == 0) { red[0][w] = v[0]; red[1][w] = v[1]; red[2][w] = v[2]; red[3][w] = v[3]; }
    __syncthreads();
    if (tid == 0) {
#pragma unroll
        for (int i = 0; i < 4; i++)
            g_part[blk * 4 + i] = red[i][0] + red[i][1] + red[i][2] + red[i][3];
    }
}

// ---------------- K4: std reduction (ddof=1) ----------------
__global__ void k_std() {
    __shared__ double sh[4][128];
    const int tid = threadIdx.x;  // 128
    double a0 = 0, a1 = 0, a2 = 0, a3 = 0;
    for (int i = tid; i < 1024; i += 128) {
        const float* p = g_part + i * 4;
        a0 += p[0]; a1 += p[1]; a2 += p[2]; a3 += p[3];
    }
    sh[0][tid] = a0; sh[1][tid] = a1; sh[2][tid] = a2; sh[3][tid] = a3;
    __syncthreads();
    for (int o = 64; o; o >>= 1) {
        if (tid < o) {
#pragma unroll
            for (int i = 0; i < 4; i++) sh[i][tid] += sh[i][tid + o];
        }
        __syncthreads();
    }
    if (tid == 0) {
        const double N = 2097152.0;
        double v1 = (sh[1][0] - sh[0][0] * sh[0][0] / N) / (N - 1.0);
        double v2 = (sh[3][0] - sh[2][0] * sh[2][0] / N) / (N - 1.0);
        g_stats[0] = (float)(1.0 / sqrt(v1));
        g_stats[1] = (float)(1.0 / sqrt(v2));
    }
}

// ---------------- K5a: h1 attention (softmax over c) ----------------
#define SM_ATT ((16384 + 2048) * 4)
__global__ void k_attn1() {
    extern __shared__ float sma[];
    float* sl = sma;            // [128 r][128 c]
    float* sv = sma + 16384;    // v2 plane [128 c][16 d]
    const int p = blockIdx.x;   // b*16+h
    const int tid = threadIdx.x; // 256
    const float inv = g_stats[0];
    const float* mp = g_ms1 + p * 16384;
    for (int idx = tid; idx < 16384; idx += 256) sl[idx] = 10.f * tanhf(mp[idx] * inv);
    const float* vp = g_v2 + p * 2048;
    for (int idx = tid; idx < 2048; idx += 256) sv[idx] = vp[idx];
    __syncthreads();

    const int w = tid >> 5, lane = tid & 31;
    for (int i = 0; i < 16; i++) {
        int r = w * 16 + i;
        float* row = sl + r * 128;
        float m = fmaxf(fmaxf(row[lane], row[lane + 32]), fmaxf(row[lane + 64], row[lane + 96]));
#pragma unroll
        for (int off = 16; off; off >>= 1) m = fmaxf(m, __shfl_xor_sync(0xffffffffu, m, off));
        float s = 0.f;
#pragma unroll
        for (int t = 0; t < 4; t++) {
            int cc = lane + t * 32;
            float e = __expf(row[cc] - m);
            row[cc] = e; s += e;
        }
#pragma unroll
        for (int off = 16; off; off >>= 1) s += __shfl_xor_sync(0xffffffffu, s, off);
        float is = 1.f / s;
#pragma unroll
        for (int t = 0; t < 4; t++) row[lane + t * 32] *= is;
    }
    __syncthreads();

    const int r = tid >> 1, d0 = (tid & 1) * 8;
    float acc[8];
#pragma unroll
    for (int j = 0; j < 8; j++) acc[j] = 0.f;
#pragma unroll 4
    for (int cc = 0; cc < 128; cc++) {
        float wgt = sl[r * 128 + cc];
        float4 v0 = *(const float4*)(sv + cc * 16 + d0);
        float4 v1 = *(const float4*)(sv + cc * 16 + d0 + 4);
        acc[0] += wgt * v0.x; acc[1] += wgt * v0.y; acc[2] += wgt * v0.z; acc[3] += wgt * v0.w;
        acc[4] += wgt * v1.x; acc[5] += wgt * v1.y; acc[6] += wgt * v1.z; acc[7] += wgt * v1.w;
    }
    const int b = p >> 4, h = p & 15;
    float* out = g_attn1 + (b * 128 + r) * 256 + h * 16 + d0;
    *(float4*)(out) = make_float4(acc[0], acc[1], acc[2], acc[3]);
    *(float4*)(out + 4) = make_float4(acc[4], acc[5], acc[6], acc[7]);
}

// ---------------- K5b: h2 attention (softmax over r, logits transposed) ----------------
__global__ void k_attn2() {
    extern __shared__ float smb[];
    float* sl = smb;
    float* sv = smb + 16384;    // v1 plane [128 r][16 d]
    const int p = blockIdx.x;
    const int tid = threadIdx.x; // 128
    const float inv = g_stats[1];
    const float* mp = g_ms2 + p * 16384;
    for (int idx = tid; idx < 16384; idx += 128) sl[idx] = 10.f * tanhf(mp[idx] * inv);
    const float* vp = g_v1 + p * 2048;
    for (int idx = tid; idx < 2048; idx += 128) sv[idx] = vp[idx];
    __syncthreads();

    const int c = tid;
    float m = -1e30f;
    for (int r = 0; r < 128; r++) m = fmaxf(m, sl[r * 128 + c]);
    float s = 0.f;
    for (int r = 0; r < 128; r++) {
        float e = __expf(sl[r * 128 + c] - m);
        sl[r * 128 + c] = e; s += e;
    }
    float is = 1.f / s;

    float acc[16];
#pragma unroll
    for (int j = 0; j < 16; j++) acc[j] = 0.f;
#pragma unroll 4
    for (int r = 0; r < 128; r++) {
        float wgt = sl[r * 128 + c] * is;
        const float4* v = (const float4*)(sv + r * 16);
        float4 v0 = v[0], v1 = v[1], v2 = v[2], v3 = v[3];
        acc[0] += wgt * v0.x; acc[1] += wgt * v0.y; acc[2] += wgt * v0.z; acc[3] += wgt * v0.w;
        acc[4] += wgt * v1.x; acc[5] += wgt * v1.y; acc[6] += wgt * v1.z; acc[7] += wgt * v1.w;
        acc[8] += wgt * v2.x; acc[9] += wgt * v2.y; acc[10] += wgt * v2.z; acc[11] += wgt * v2.w;
        acc[12] += wgt * v3.x; acc[13] += wgt * v3.y; acc[14] += wgt * v3.z; acc[15] += wgt * v3.w;
    }
    const int b = p >> 4, h = p & 15;
    float* out = g_attn2 + (b * 128 + c) * 256 + h * 16;
    *(float4*)(out) = make_float4(acc[0], acc[1], acc[2], acc[3]);
    *(float4*)(out + 4) = make_float4(acc[4], acc[5], acc[6], acc[7]);
    *(float4*)(out + 8) = make_float4(acc[8], acc[9], acc[10], acc[11]);
    *(float4*)(out + 12) = make_float4(acc[12], acc[13], acc[14], acc[15]);
}

// ---------------- K6: output projections ----------------
// rows 0..1023: attn1 @ out1_w -> d_out[0:262144); rows 1024..2047: attn2 @ out2_w -> +262144
#define SM_OUT ((32 * 260 + 256 * 64) * 4)
__global__ void k_out(const float* __restrict__ o1w, const float* __restrict__ o2w,
                      float* __restrict__ out) {
    extern __shared__ float smo[];
    float* sA = smo;
    float* sB = smo + 32 * 260;
    const int m0 = blockIdx.x * 32, n0 = blockIdx.y * 64;
    const bool first = (m0 < 1024);
    const float* A = first ? g_attn1 : g_attn2;
    const float* W = first ? o1w : o2w;
    float* dst = out + (first ? 0 : 262144);
    const int mm = m0 & 1023;
    const int tid = threadIdx.x;

    for (int idx = tid; idx < 2048; idx += 256) {
        int row = idx >> 6, kk = (idx & 63) << 2;
        float4 v = *(const float4*)(A + (mm + row) * 256 + kk);
        *(float4*)(sA + row * 260 + kk) = v;
    }
    for (int idx = tid; idx < 4096; idx += 256) {
        int row = idx >> 4, c4 = (idx & 15) << 2;
        float4 v = *(const float4*)(W + row * 256 + n0 + c4);
        *(float4*)(sB + row * 64 + c4) = v;
    }
    __syncthreads();

    const int r = tid >> 3, cg = tid & 7;
    float acc[8];
#pragma unroll
    for (int j = 0; j < 8; j++) acc[j] = 0.f;
    const float4* sB4 = (const float4*)sB;
#pragma unroll 4
    for (int k = 0; k < 256; k++) {
        float a = sA[r * 260 + k];
        float4 b0 = sB4[k * 16 + cg * 2];
        float4 b1 = sB4[k * 16 + cg * 2 + 1];
        acc[0] += a * b0.x; acc[1] += a * b0.y; acc[2] += a * b0.z; acc[3] += a * b0.w;
        acc[4] += a * b1.x; acc[5] += a * b1.y; acc[6] += a * b1.z; acc[7] += a * b1.w;
    }
    float* o = dst + (mm + r) * 256 + n0 + cg * 8;
    *(float4*)(o) = make_float4(acc[0], acc[1], acc[2], acc[3]);
    *(float4*)(o + 4) = make_float4(acc[4], acc[5], acc[6], acc[7]);
}

// ---------------- launch ----------------
extern "C" void kernel_launch(void* const* d_in, const int* in_sizes, int n_in,
                              void* d_out, int out_size) {
    const float* x1   = (const float*)d_in[0];
    const float* x2   = (const float*)d_in[1];
    const float* cost = (const float*)d_in[2];
    const float* Wqv1 = (const float*)d_in[3];
    const float* lin1 = (const float*)d_in[4];
    const float* lin2 = (const float*)d_in[5];
    const float* o1w  = (const float*)d_in[6];
    const float* o2w  = (const float*)d_in[7];
    float* out = (float*)d_out;

    cudaFuncSetAttribute(k_qkv,   cudaFuncAttributeMaxDynamicSharedMemorySize, SM_QKV);
    cudaFuncSetAttribute(k_mlp,   cudaFuncAttributeMaxDynamicSharedMemorySize, SM_MLP);
    cudaFuncSetAttribute(k_attn1, cudaFuncAttributeMaxDynamicSharedMemorySize, SM_ATT);
    cudaFuncSetAttribute(k_attn2, cudaFuncAttributeMaxDynamicSharedMemorySize, SM_ATT);
    cudaFuncSetAttribute(k_out,   cudaFuncAttributeMaxDynamicSharedMemorySize, SM_OUT);

    k_qkv<<<dim3(64, 8), 256, SM_QKV>>>(x1, x2, Wqv1);
    k_mlp<<<1024, 128, SM_MLP>>>(cost, lin1, lin2);
    k_std<<<1, 128>>>();
    k_attn1<<<128, 256, SM_ATT>>>();
    k_attn2<<<128, 128, SM_ATT>>>();
    k_out<<<dim3(64, 4), 256, SM_OUT>>>(o1w, o2w, out);

    (void)in_sizes; (void)n_in; (void)out_size;
}

// round 2
// speedup vs baseline: 1.1244x; 1.1244x over previous
#include <cuda_runtime.h>
#include <math.h>

typedef unsigned long long ull;

// ---------------- scratch (device globals; no allocations allowed) ----------------
__device__ float g_qT  [1024 * 256];      // [b*128+r][e]   e = h*16+d
__device__ float g_kTT [8 * 256 * 128];   // [b][e][c]
__device__ float g_v1  [1024 * 256];      // [b][h][s][d]
__device__ float g_v2  [1024 * 256];      // [b][h][s][d]
__device__ float g_ms1 [2097152];         // [b][h][r][c]
__device__ float g_ms2 [2097152];         // [b][h][r][c]
__device__ float g_attn1[1024 * 256];     // [b*128+r][h*16+d]
__device__ float g_attn2[1024 * 256];     // [b*128+c][h*16+d]
__device__ float g_part[1024 * 4];        // per-block {s1,q1,s2,q2}
__device__ float g_stats[2];              // inv_std1, inv_std2

// ---------------- f32x2 packed helpers (Blackwell sm_100+) ----------------
__device__ __forceinline__ ull pack2(float lo, float hi) {
    ull r; asm("mov.b64 %0, {%1, %2};" : "=l"(r) : "f"(lo), "f"(hi)); return r;
}
__device__ __forceinline__ void unpack2(ull v, float& lo, float& hi) {
    asm("mov.b64 {%0, %1}, %2;" : "=f"(lo), "=f"(hi) : "l"(v));
}
__device__ __forceinline__ ull fma2(ull a, ull b, ull c) {
    ull d; asm("fma.rn.f32x2 %0, %1, %2, %3;" : "=l"(d) : "l"(a), "l"(b), "l"(c)); return d;
}
__device__ __forceinline__ ull mul2(ull a, ull b) {
    ull d; asm("mul.rn.f32x2 %0, %1, %2;" : "=l"(d) : "l"(a), "l"(b)); return d;
}

// ---------------- K1: qkv projection GEMM ----------------
// M=2048 (x1 rows then x2 rows), N=512, K=256. 32x64 tiles, 256 threads.
#define SM_QKV ((32 * 260 + 256 * 64) * 4)
__global__ void k_qkv(const float* __restrict__ x1, const float* __restrict__ x2,
                      const float* __restrict__ W) {
    extern __shared__ float smq[];
    float* sA = smq;             // 32 x 260 (padded)
    float* sB = smq + 32 * 260;  // 256 x 64
    const int m0 = blockIdx.x * 32, n0 = blockIdx.y * 64;
    const bool isX1 = (m0 < 1024);
    const float* src = isX1 ? x1 : x2;
    const int mm = m0 & 1023;
    const int b = mm >> 7, s0 = mm & 127;
    const int tid = threadIdx.x;

    for (int idx = tid; idx < 2048; idx += 256) {
        int row = idx >> 6, kk = (idx & 63) << 2;
        float4 v = *(const float4*)(src + (b * 128 + s0 + row) * 256 + kk);
        *(float4*)(sA + row * 260 + kk) = v;
    }
    for (int idx = tid; idx < 4096; idx += 256) {
        int row = idx >> 4, c4 = (idx & 15) << 2;
        float4 v = *(const float4*)(W + row * 512 + n0 + c4);
        *(float4*)(sB + row * 64 + c4) = v;
    }
    __syncthreads();

    const int r = tid >> 3, cg = tid & 7;
    float acc[8];
#pragma unroll
    for (int j = 0; j < 8; j++) acc[j] = 0.f;
    const float4* sB4 = (const float4*)sB;
#pragma unroll 4
    for (int k = 0; k < 256; k++) {
        float a = sA[r * 260 + k];
        float4 b0 = sB4[k * 16 + cg * 2];
        float4 b1 = sB4[k * 16 + cg * 2 + 1];
        acc[0] += a * b0.x; acc[1] += a * b0.y; acc[2] += a * b0.z; acc[3] += a * b0.w;
        acc[4] += a * b1.x; acc[5] += a * b1.y; acc[6] += a * b1.z; acc[7] += a * b1.w;
    }

    const int s = s0 + r;
#pragma unroll
    for (int j = 0; j < 8; j++) {
        int n = n0 + cg * 8 + j;
        float v = acc[j];
        if (n < 256) {
            if (isX1) g_qT[(b * 128 + s) * 256 + n] = v;
            else      g_kTT[(b * 256 + n) * 128 + s] = v;
        } else {
            int h = (n - 256) >> 4, d = n & 15;
            float* dst = isX1 ? g_v1 : g_v2;
            dst[((b * 16 + h) * 128 + s) * 16 + d] = v;
        }
    }
}

// ---------------- K3: fused dot + MixedScoreFF MLP ----------------
// grid 512 = (b, r-pair), block 256 = (2 r) x (128 c). f32x2 packed MLP, weights in SMEM.
#define SM_MLP 102400
__global__ void k_mlp(const float* __restrict__ cost, const float* __restrict__ w1,
                      const float* __restrict__ w2) {
    extern __shared__ char smm[];
    ull*   sw1p = (ull*)smm;                  // [kp=256][h=16]  pairs of W1 even-row cols
    ull*   scbp = (ull*)(smm + 32768);        // [256] cost-bias pairs
    ull*   sw2  = (ull*)(smm + 34816);        // [512][16] lin2 rows as float2 pairs
    float* sq   = (float*)(smm + 100352);     // [512] two q rows

    const int blk = blockIdx.x;               // 512
    const int b = blk >> 6, r0 = (blk & 63) << 1;
    const int tid = threadIdx.x;              // 256
    const int rsel = tid >> 7, c = tid & 127;
    const int r = r0 + rsel;

    for (int idx = tid; idx < 4096; idx += 256) {
        int h = idx >> 8, kp = idx & 255;
        sw1p[kp * 16 + h] = *(const ull*)(w1 + h * 1024 + 2 * kp);
    }
    if (tid < 256) {
        int kp = tid;
        float c0 = 0.f, c1 = 0.f;
#pragma unroll
        for (int h = 0; h < 16; h++) {
            c0 += w1[(2 * h + 1) * 512 + 2 * kp];
            c1 += w1[(2 * h + 1) * 512 + 2 * kp + 1];
        }
        scbp[kp] = pack2(c0, c1);
    }
    {
        const ull* w2u = (const ull*)w2;
        for (int idx = tid; idx < 8192; idx += 256) sw2[idx] = w2u[idx];
    }
    for (int idx = tid; idx < 512; idx += 256) sq[idx] = g_qT[(b * 128 + r0) * 256 + idx];
    __syncthreads();

    // dot logits: din[h] = 0.25 * sum_d q[h,d] * k[h,d]
    float din[16];
    const float* kbase = g_kTT + b * 32768 + c;
    const float* sqr = sq + rsel * 256;
#pragma unroll
    for (int h = 0; h < 16; h++) {
        float a = 0.f;
#pragma unroll
        for (int d = 0; d < 16; d++) a += sqr[h * 16 + d] * kbase[(h * 16 + d) * 128];
        din[h] = a * 0.25f;
    }
    ull din2[16];
#pragma unroll
    for (int h = 0; h < 16; h++) din2[h] = pack2(din[h], din[h]);
    float cv = cost[(b * 128 + r) * 128 + c];
    ull cost2 = pack2(cv, cv);

    ull o2[16];
#pragma unroll
    for (int j = 0; j < 16; j++) o2[j] = 0ull;

#pragma unroll 4
    for (int kp = 0; kp < 256; kp++) {
        ull hp = mul2(cost2, scbp[kp]);
        const ull* w1c = sw1p + kp * 16;
#pragma unroll
        for (int h = 0; h < 16; h++) hp = fma2(din2[h], w1c[h], hp);
        float h0, h1; unpack2(hp, h0, h1);
        h0 = fmaxf(h0, 0.f); h1 = fmaxf(h1, 0.f);
        ull h0x = pack2(h0, h0), h1x = pack2(h1, h1);
        const ull* w2a = sw2 + (kp * 2) * 16;
        const ull* w2b = w2a + 16;
#pragma unroll
        for (int j = 0; j < 16; j++) {
            o2[j] = fma2(h0x, w2a[j], o2[j]);
            o2[j] = fma2(h1x, w2b[j], o2[j]);
        }
    }

    float s1 = 0.f, q1 = 0.f, s2 = 0.f, q2 = 0.f;
#pragma unroll
    for (int h = 0; h < 16; h++) {
        float m1, m2; unpack2(o2[h], m1, m2);
        int idx = ((b * 16 + h) * 128 + r) * 128 + c;
        g_ms1[idx] = m1;
        g_ms2[idx] = m2;
        s1 += m1; q1 += m1 * m1; s2 += m2; q2 += m2 * m2;
    }

    // block reduce -> g_part
    float v[4] = {s1, q1, s2, q2};
#pragma unroll
    for (int i = 0; i < 4; i++)
        for (int off = 16; off; off >>= 1) v[i] += __shfl_xor_sync(0xffffffffu, v[i], off);
    __shared__ float red[4][8];
    int w = tid >> 5, lane = tid & 31;
    if (lane == 0) { red[0][w] = v[0]; red[1][w] = v[1]; red[2][w] = v[2]; red[3][w] = v[3]; }
    __syncthreads();
    if (tid == 0) {
#pragma unroll
        for (int i = 0; i < 4; i++) {
            float s = 0.f;
#pragma unroll
            for (int j = 0; j < 8; j++) s += red[i][j];
            g_part[blk * 4 + i] = s;
        }
    }
}

// ---------------- K4: std reduction (ddof=1) ----------------
__global__ void k_std() {
    __shared__ double sh[4][128];
    const int tid = threadIdx.x;  // 128
    double a0 = 0, a1 = 0, a2 = 0, a3 = 0;
    for (int i = tid; i < 512; i += 128) {
        const float* p = g_part + i * 4;
        a0 += p[0]; a1 += p[1]; a2 += p[2]; a3 += p[3];
    }
    sh[0][tid] = a0; sh[1][tid] = a1; sh[2][tid] = a2; sh[3][tid] = a3;
    __syncthreads();
    for (int o = 64; o; o >>= 1) {
        if (tid < o) {
#pragma unroll
            for (int i = 0; i < 4; i++) sh[i][tid] += sh[i][tid + o];
        }
        __syncthreads();
    }
    if (tid == 0) {
        const double N = 2097152.0;
        double v1 = (sh[1][0] - sh[0][0] * sh[0][0] / N) / (N - 1.0);
        double v2 = (sh[3][0] - sh[2][0] * sh[2][0] / N) / (N - 1.0);
        g_stats[0] = (float)(1.0 / sqrt(v1));
        g_stats[1] = (float)(1.0 / sqrt(v2));
    }
}

// ---------------- K5a: h1 attention (softmax over c), 2 blocks per plane ----------------
#define SM_AT1 ((64 * 128 + 128 * 16) * 4)
__global__ void k_attn1() {
    extern __shared__ float sma[];
    float* sl = sma;            // [64 r][128 c]
    float* sv = sma + 8192;     // v2 plane [128 c][16 d]
    const int blk = blockIdx.x;      // 256
    const int p = blk >> 1, rh = blk & 1;
    const int tid = threadIdx.x;     // 256
    const float inv = g_stats[0];
    const float* mp = g_ms1 + p * 16384 + rh * 8192;
    for (int idx = tid; idx < 8192; idx += 256) sl[idx] = 10.f * tanhf(mp[idx] * inv);
    const float* vp = g_v2 + p * 2048;
    for (int idx = tid; idx < 2048; idx += 256) sv[idx] = vp[idx];
    __syncthreads();

    const int w = tid >> 5, lane = tid & 31;
#pragma unroll
    for (int i = 0; i < 8; i++) {
        int r = w * 8 + i;
        float* row = sl + r * 128;
        float m = fmaxf(fmaxf(row[lane], row[lane + 32]), fmaxf(row[lane + 64], row[lane + 96]));
#pragma unroll
        for (int off = 16; off; off >>= 1) m = fmaxf(m, __shfl_xor_sync(0xffffffffu, m, off));
        float s = 0.f;
#pragma unroll
        for (int t = 0; t < 4; t++) {
            int cc = lane + t * 32;
            float e = __expf(row[cc] - m);
            row[cc] = e; s += e;
        }
#pragma unroll
        for (int off = 16; off; off >>= 1) s += __shfl_xor_sync(0xffffffffu, s, off);
        float is = 1.f / s;
#pragma unroll
        for (int t = 0; t < 4; t++) row[lane + t * 32] *= is;
    }
    __syncthreads();

    const int r = tid >> 2, d0 = (tid & 3) << 2;
    float a0 = 0.f, a1 = 0.f, a2 = 0.f, a3 = 0.f;
#pragma unroll 4
    for (int cc = 0; cc < 128; cc++) {
        float wgt = sl[r * 128 + cc];
        float4 v = *(const float4*)(sv + cc * 16 + d0);
        a0 += wgt * v.x; a1 += wgt * v.y; a2 += wgt * v.z; a3 += wgt * v.w;
    }
    const int b = p >> 4, h = p & 15;
    float* out = g_attn1 + (b * 128 + rh * 64 + r) * 256 + h * 16 + d0;
    *(float4*)out = make_float4(a0, a1, a2, a3);
}

// ---------------- K5b: h2 attention (softmax over r), 2 blocks per plane ----------------
// floats: sl 8192 + sv 2048 + pr 4096 + redm 256 + reds 256 = 14848
#define SM_AT2 (14848 * 4)
__global__ void k_attn2() {
    extern __shared__ float smb[];
    float* sl   = smb;              // [128 r][64 c]
    float* sv   = smb + 8192;       // v1 plane [128 r][16 d]
    float* pr   = smb + 10240;      // [4 seg][64 c][16 d]
    float* redm = smb + 14336;      // [4 seg][64 c]
    float* reds = smb + 14592;      // [4 seg][64 c]
    const int blk = blockIdx.x;     // 256
    const int p = blk >> 1, ch = blk & 1;
    const int tid = threadIdx.x;    // 256
    const float inv = g_stats[1];
    const float* mp = g_ms2 + p * 16384 + ch * 64;
    for (int idx = tid; idx < 8192; idx += 256)
        sl[idx] = 10.f * tanhf(mp[(idx >> 6) * 128 + (idx & 63)] * inv);
    const float* vp = g_v1 + p * 2048;
    for (int idx = tid; idx < 2048; idx += 256) sv[idx] = vp[idx];
    __syncthreads();

    const int c = tid & 63, seg = tid >> 6;   // seg owns rows [seg*32, seg*32+32)
    float m = -1e30f;
#pragma unroll 4
    for (int i = 0; i < 32; i++) m = fmaxf(m, sl[(seg * 32 + i) * 64 + c]);
    redm[seg * 64 + c] = m;
    __syncthreads();
    m = fmaxf(fmaxf(redm[c], redm[64 + c]), fmaxf(redm[128 + c], redm[192 + c]));
    float s = 0.f;
#pragma unroll 4
    for (int i = 0; i < 32; i++) {
        int rr = seg * 32 + i;
        float e = __expf(sl[rr * 64 + c] - m);
        sl[rr * 64 + c] = e; s += e;
    }
    reds[seg * 64 + c] = s;

    float acc[16];
#pragma unroll
    for (int j = 0; j < 16; j++) acc[j] = 0.f;
#pragma unroll 2
    for (int i = 0; i < 32; i++) {
        int rr = seg * 32 + i;
        float wgt = sl[rr * 64 + c];
        const float4* v = (const float4*)(sv + rr * 16);
        float4 v0 = v[0], v1 = v[1], v2 = v[2], v3 = v[3];
        acc[0] += wgt * v0.x; acc[1] += wgt * v0.y; acc[2] += wgt * v0.z; acc[3] += wgt * v0.w;
        acc[4] += wgt * v1.x; acc[5] += wgt * v1.y; acc[6] += wgt * v1.z; acc[7] += wgt * v1.w;
        acc[8] += wgt * v2.x; acc[9] += wgt * v2.y; acc[10] += wgt * v2.z; acc[11] += wgt * v2.w;
        acc[12] += wgt * v3.x; acc[13] += wgt * v3.y; acc[14] += wgt * v3.z; acc[15] += wgt * v3.w;
    }
    float* prp = pr + (seg * 64 + c) * 16;
#pragma unroll
    for (int j = 0; j < 4; j++)
        *(float4*)(prp + j * 4) = make_float4(acc[j * 4], acc[j * 4 + 1], acc[j * 4 + 2], acc[j * 4 + 3]);
    __syncthreads();

    const int b = p >> 4, h = p & 15;
    for (int o = tid; o < 1024; o += 256) {
        int cc = o >> 4, d = o & 15;
        float v = pr[(cc) * 16 + d] + pr[(64 + cc) * 16 + d]
                + pr[(128 + cc) * 16 + d] + pr[(192 + cc) * 16 + d];
        float stot = reds[cc] + reds[64 + cc] + reds[128 + cc] + reds[192 + cc];
        g_attn2[(b * 128 + ch * 64 + cc) * 256 + h * 16 + d] = v / stot;
    }
}

// ---------------- K6: output projections ----------------
#define SM_OUT ((32 * 260 + 256 * 64) * 4)
__global__ void k_out(const float* __restrict__ o1w, const float* __restrict__ o2w,
                      float* __restrict__ out) {
    extern __shared__ float smo[];
    float* sA = smo;
    float* sB = smo + 32 * 260;
    const int m0 = blockIdx.x * 32, n0 = blockIdx.y * 64;
    const bool first = (m0 < 1024);
    const float* A = first ? g_attn1 : g_attn2;
    const float* W = first ? o1w : o2w;
    float* dst = out + (first ? 0 : 262144);
    const int mm = m0 & 1023;
    const int tid = threadIdx.x;

    for (int idx = tid; idx < 2048; idx += 256) {
        int row = idx >> 6, kk = (idx & 63) << 2;
        float4 v = *(const float4*)(A + (mm + row) * 256 + kk);
        *(float4*)(sA + row * 260 + kk) = v;
    }
    for (int idx = tid; idx < 4096; idx += 256) {
        int row = idx >> 4, c4 = (idx & 15) << 2;
        float4 v = *(const float4*)(W + row * 256 + n0 + c4);
        *(float4*)(sB + row * 64 + c4) = v;
    }
    __syncthreads();

    const int r = tid >> 3, cg = tid & 7;
    float acc[8];
#pragma unroll
    for (int j = 0; j < 8; j++) acc[j] = 0.f;
    const float4* sB4 = (const float4*)sB;
#pragma unroll 4
    for (int k = 0; k < 256; k++) {
        float a = sA[r * 260 + k];
        float4 b0 = sB4[k * 16 + cg * 2];
        float4 b1 = sB4[k * 16 + cg * 2 + 1];
        acc[0] += a * b0.x; acc[1] += a * b0.y; acc[2] += a * b0.z; acc[3] += a * b0.w;
        acc[4] += a * b1.x; acc[5] += a * b1.y; acc[6] += a * b1.z; acc[7] += a * b1.w;
    }
    float* o = dst + (mm + r) * 256 + n0 + cg * 8;
    *(float4*)(o) = make_float4(acc[0], acc[1], acc[2], acc[3]);
    *(float4*)(o + 4) = make_float4(acc[4], acc[5], acc[6], acc[7]);
}

// ---------------- launch ----------------
extern "C" void kernel_launch(void* const* d_in, const int* in_sizes, int n_in,
                              void* d_out, int out_size) {
    const float* x1   = (const float*)d_in[0];
    const float* x2   = (const float*)d_in[1];
    const float* cost = (const float*)d_in[2];
    const float* Wqv1 = (const float*)d_in[3];
    const float* lin1 = (const float*)d_in[4];
    const float* lin2 = (const float*)d_in[5];
    const float* o1w  = (const float*)d_in[6];
    const float* o2w  = (const float*)d_in[7];
    float* out = (float*)d_out;

    cudaFuncSetAttribute(k_qkv,   cudaFuncAttributeMaxDynamicSharedMemorySize, SM_QKV);
    cudaFuncSetAttribute(k_mlp,   cudaFuncAttributeMaxDynamicSharedMemorySize, SM_MLP);
    cudaFuncSetAttribute(k_attn1, cudaFuncAttributeMaxDynamicSharedMemorySize, SM_AT1);
    cudaFuncSetAttribute(k_attn2, cudaFuncAttributeMaxDynamicSharedMemorySize, SM_AT2);
    cudaFuncSetAttribute(k_out,   cudaFuncAttributeMaxDynamicSharedMemorySize, SM_OUT);

    k_qkv<<<dim3(64, 8), 256, SM_QKV>>>(x1, x2, Wqv1);
    k_mlp<<<512, 256, SM_MLP>>>(cost, lin1, lin2);
    k_std<<<1, 128>>>();
    k_attn1<<<256, 256, SM_AT1>>>();
    k_attn2<<<256, 256, SM_AT2>>>();
    k_out<<<dim3(64, 4), 256, SM_OUT>>>(o1w, o2w, out);

    (void)in_sizes; (void)n_in; (void)out_size;
}